// round 1
// baseline (speedup 1.0000x reference)
#include <cuda_runtime.h>

// Problem constants
#define NB 2
#define NC 128
#define NS 2048
#define NZT 256
#define NXT 256
#define NKK 4
#define MPX (NZT * NXT)          // 65536 pixels per batch

#define THREADS 256
#define PXT 4                    // pixels per thread
#define TILE_PX (THREADS * PXT)  // 1024 pixels per CTA
#define TILES (MPX / TILE_PX)    // 64 tiles per batch

#define SMEM_BYTES (2 * NS * 16 + NC * 3 * 4)   // double-buffered rf rows + pr cache

__device__ __forceinline__ unsigned smem_u32(const void* p) {
    unsigned a;
    asm("{ .reg .u64 t; cvta.to.shared.u64 t, %1; cvt.u32.u64 %0, t; }"
        : "=r"(a) : "l"(p));
    return a;
}
__device__ __forceinline__ void cp16(unsigned s, const void* g) {
    asm volatile("cp.async.cg.shared.global [%0], [%1], 16;" :: "r"(s), "l"(g));
}
__device__ __forceinline__ void cp_commit() {
    asm volatile("cp.async.commit_group;");
}
template <int N>
__device__ __forceinline__ void cp_wait() {
    asm volatile("cp.async.wait_group %0;" :: "n"(N));
}

extern __shared__ char smem_raw[];

__global__ __launch_bounds__(THREADS, 1)
void das_beamform_kernel(const float* __restrict__ rf,
                         const float* __restrict__ g,
                         const float* __restrict__ pr,
                         const float* __restrict__ p,
                         float* __restrict__ out)
{
    float4* sbuf = reinterpret_cast<float4*>(smem_raw);                 // [2][NS] float4
    float*  s_pr = reinterpret_cast<float*>(smem_raw + 2 * NS * 16);    // [NC*3]

    const int b = blockIdx.y;
    const int tile0 = blockIdx.x * TILE_PX;
    const int tid = threadIdx.x;

    // Acquisition params (uniform per batch)
    const float c0 = p[b * 4 + 0];
    const float fs = p[b * 4 + 1];
    const float t0 = p[b * 4 + 2];
    const float scale = fs / c0;          // samples per meter
    const float toff  = t0 * scale;       // fs*t0/c0

    // Cache receiver positions for this batch
    for (int i = tid; i < NC * 3; i += THREADS)
        s_pr[i] = pr[(size_t)b * NC * 3 + i];

    // Per-pixel registers: coordinates, tx-path base sample, accumulators
    float gx[PXT], gy[PXT], gz[PXT], base[PXT];
    float4 acc[PXT];
#pragma unroll
    for (int q = 0; q < PXT; q++) {
        int m = tile0 + tid + q * THREADS;
        const float* gp = g + ((size_t)b * MPX + m) * 3;
        gx[q] = gp[0];
        gy[q] = gp[1];
        gz[q] = gp[2];
        base[q] = fmaf(scale, gz[q], toff);   // scale * d_tx + scale * t0
        acc[q] = make_float4(0.f, 0.f, 0.f, 0.f);
    }

    // rf viewed as float4 rows: one channel = NS rows of K=4 floats
    const float4* rfb = reinterpret_cast<const float4*>(rf) + (size_t)b * NC * NS;

    // Preload channel 0 into buffer 0
    {
        const float4* src = rfb;
#pragma unroll
        for (int j = 0; j < NS / THREADS; j++)
            cp16(smem_u32(&sbuf[tid + j * THREADS]), src + tid + j * THREADS);
        cp_commit();
    }

    for (int c = 0; c < NC; c++) {
        // All warps done reading buffer of parity (c+1)&1 (used in iter c-1)
        __syncthreads();

        if (c + 1 < NC) {
            const float4* src = rfb + (size_t)(c + 1) * NS;
            float4* dst = sbuf + ((c + 1) & 1) * NS;
#pragma unroll
            for (int j = 0; j < NS / THREADS; j++)
                cp16(smem_u32(&dst[tid + j * THREADS]), src + tid + j * THREADS);
            cp_commit();
            cp_wait<1>();   // channel c's fill group complete
        } else {
            cp_wait<0>();
        }
        __syncthreads();    // channel-c data visible to all threads

        const float4* buf = sbuf + (c & 1) * NS;
        const float prx = s_pr[c * 3 + 0];
        const float pry = s_pr[c * 3 + 1];
        const float prz = s_pr[c * 3 + 2];

#pragma unroll
        for (int q = 0; q < PXT; q++) {
            float dx = gx[q] - prx;
            float dy = gy[q] - pry;
            float dz = gz[q] - prz;
            float d2 = fmaf(dx, dx, fmaf(dy, dy, dz * dz));
            float dr = sqrtf(d2);                       // receive path length
            float s  = fmaf(scale, dr, base[q]);        // fractional sample idx
            s = fminf(fmaxf(s, 0.0f), (float)(NS - 1));
            int i0 = (int)s;                            // trunc == floor (s >= 0)
            i0 = min(i0, NS - 2);
            float w = s - (float)i0;

            float4 y0 = buf[i0];
            float4 y1 = buf[i0 + 1];
            acc[q].x = fmaf(w, y1.x - y0.x, acc[q].x + y0.x);
            acc[q].y = fmaf(w, y1.y - y0.y, acc[q].y + y0.y);
            acc[q].z = fmaf(w, y1.z - y0.z, acc[q].z + y0.z);
            acc[q].w = fmaf(w, y1.w - y0.w, acc[q].w + y0.w);
        }
    }

    float4* outp = reinterpret_cast<float4*>(out) + (size_t)b * MPX;
#pragma unroll
    for (int q = 0; q < PXT; q++) {
        int m = tile0 + tid + q * THREADS;
        outp[m] = acc[q];
    }
}

extern "C" void kernel_launch(void* const* d_in, const int* in_sizes, int n_in,
                              void* d_out, int out_size)
{
    const float* rf = (const float*)d_in[0];   // [B, Nc, Ns, K]
    const float* g  = (const float*)d_in[1];   // [B, Nz, Nx, 3]
    const float* pr = (const float*)d_in[2];   // [B, Nc, 3]
    const float* p  = (const float*)d_in[3];   // [B, 4]
    float* out = (float*)d_out;                // [B, Nz, Nx, K]

    cudaFuncSetAttribute(das_beamform_kernel,
                         cudaFuncAttributeMaxDynamicSharedMemorySize, SMEM_BYTES);

    dim3 grid(TILES, NB);
    das_beamform_kernel<<<grid, THREADS, SMEM_BYTES>>>(rf, g, pr, p, out);
}

// round 2
// speedup vs baseline: 1.8335x; 1.8335x over previous
#include <cuda_runtime.h>
#include <cuda_fp16.h>

// Problem constants
#define NB 2
#define NC 128
#define NS 2048
#define MPX 65536                // Nz*Nx pixels per batch
#define NKK 4

#define THREADS 256
#define PXT 4                    // pixels per thread
#define TILE_PX (THREADS * PXT)  // 1024 pixels per CTA
#define TILES (MPX / TILE_PX)    // 64 tiles per batch

#define SPLIT 4
#define CPC (NC / SPLIT)         // 32 channels per CTA

// fp16 rf row = NS * 4 halves = 16KB per channel; double buffered
#define SMEM_BYTES (2 * NS * 8 + CPC * 3 * 4)

// Static device scratch (no allocations allowed)
__device__ __half g_rf16[(size_t)NB * NC * NS * NKK];           // 4.2 MB
__device__ float  g_part[(size_t)SPLIT * NB * MPX * NKK];       // 8.4 MB

__device__ __forceinline__ unsigned smem_u32(const void* p) {
    unsigned a;
    asm("{ .reg .u64 t; cvta.to.shared.u64 t, %1; cvt.u32.u64 %0, t; }"
        : "=r"(a) : "l"(p));
    return a;
}
__device__ __forceinline__ void cp16(unsigned s, const void* g) {
    asm volatile("cp.async.cg.shared.global [%0], [%1], 16;" :: "r"(s), "l"(g));
}
__device__ __forceinline__ void cp_commit() {
    asm volatile("cp.async.commit_group;");
}
template <int N>
__device__ __forceinline__ void cp_wait() {
    asm volatile("cp.async.wait_group %0;" :: "n"(N));
}

// ---------------------------------------------------------------------------
// Kernel 1: convert rf fp32 -> fp16 scratch. One thread per sample-row (K=4).
// ---------------------------------------------------------------------------
__global__ void convert_rf_kernel(const float4* __restrict__ rf4) {
    int idx = blockIdx.x * blockDim.x + threadIdx.x;   // over NB*NC*NS rows
    float4 v = rf4[idx];
    __half2 lo = __floats2half2_rn(v.x, v.y);
    __half2 hi = __floats2half2_rn(v.z, v.w);
    uint2 packed;
    packed.x = *reinterpret_cast<unsigned*>(&lo);
    packed.y = *reinterpret_cast<unsigned*>(&hi);
    reinterpret_cast<uint2*>(g_rf16)[idx] = packed;
}

// ---------------------------------------------------------------------------
// Kernel 2: main DAS beamform over a channel slice, writes partial sums.
// ---------------------------------------------------------------------------
extern __shared__ char smem_raw[];

__global__ __launch_bounds__(THREADS, 4)
void das_beamform_kernel(const float* __restrict__ g,
                         const float* __restrict__ pr,
                         const float* __restrict__ p)
{
    uint2* sbuf = reinterpret_cast<uint2*>(smem_raw);             // [2][NS]
    float* s_pr = reinterpret_cast<float*>(smem_raw + 2 * NS * 8);

    const int b     = blockIdx.y;
    const int sp    = blockIdx.z;
    const int tile0 = blockIdx.x * TILE_PX;
    const int tid   = threadIdx.x;
    const int c0    = sp * CPC;

    const float c0v = p[b * 4 + 0];
    const float fs  = p[b * 4 + 1];
    const float t0  = p[b * 4 + 2];
    const float scale = fs / c0v;
    const float toff  = t0 * scale;

    // Cache this slice's receiver positions
    if (tid < CPC * 3)
        s_pr[tid] = pr[((size_t)b * NC + c0) * 3 + tid];

    float gx[PXT], gy[PXT], gz[PXT], base[PXT];
    float4 acc[PXT];
#pragma unroll
    for (int q = 0; q < PXT; q++) {
        int m = tile0 + tid + q * THREADS;
        const float* gp = g + ((size_t)b * MPX + m) * 3;
        gx[q] = gp[0];
        gy[q] = gp[1];
        gz[q] = gp[2];
        base[q] = fmaf(scale, gz[q], toff);
        acc[q] = make_float4(0.f, 0.f, 0.f, 0.f);
    }

    // fp16 rf rows for this (batch, slice): uint2 per sample-row
    const uint4* rfb = reinterpret_cast<const uint4*>(g_rf16) +
                       ((size_t)b * NC + c0) * (NS / 2);   // 16B chunks, NS/2 per row

    // Preload channel c0 into buffer 0 (1024 chunks of 16B)
    {
        const uint4* src = rfb;
        unsigned dst = smem_u32(sbuf);
#pragma unroll
        for (int j = 0; j < (NS / 2) / THREADS; j++)
            cp16(dst + (tid + j * THREADS) * 16, src + tid + j * THREADS);
        cp_commit();
    }

    for (int cc = 0; cc < CPC; cc++) {
        __syncthreads();   // readers of buffer (cc+1)&1 from iter cc-1 are done

        if (cc + 1 < CPC) {
            const uint4* src = rfb + (size_t)(cc + 1) * (NS / 2);
            unsigned dst = smem_u32(sbuf + ((cc + 1) & 1) * NS);
#pragma unroll
            for (int j = 0; j < (NS / 2) / THREADS; j++)
                cp16(dst + (tid + j * THREADS) * 16, src + tid + j * THREADS);
            cp_commit();
            cp_wait<1>();   // channel cc's fill group complete
        } else {
            cp_wait<0>();
        }
        __syncthreads();

        const uint2* buf = sbuf + (cc & 1) * NS;
        const float prx = s_pr[cc * 3 + 0];
        const float pry = s_pr[cc * 3 + 1];
        const float prz = s_pr[cc * 3 + 2];

#pragma unroll
        for (int q = 0; q < PXT; q++) {
            float dx = gx[q] - prx;
            float dy = gy[q] - pry;
            float dz = gz[q] - prz;
            float d2 = fmaf(dx, dx, fmaf(dy, dy, dz * dz));
            float dr = sqrtf(d2);
            float s  = fmaf(scale, dr, base[q]);
            s = fminf(fmaxf(s, 0.0f), (float)(NS - 1));
            int i0 = (int)s;
            i0 = min(i0, NS - 2);
            float w = s - (float)i0;

            uint2 r0 = buf[i0];
            uint2 r1 = buf[i0 + 1];
            float2 a0 = __half22float2(*reinterpret_cast<__half2*>(&r0.x));
            float2 b0 = __half22float2(*reinterpret_cast<__half2*>(&r0.y));
            float2 a1 = __half22float2(*reinterpret_cast<__half2*>(&r1.x));
            float2 b1 = __half22float2(*reinterpret_cast<__half2*>(&r1.y));

            acc[q].x = fmaf(w, a1.x - a0.x, acc[q].x + a0.x);
            acc[q].y = fmaf(w, a1.y - a0.y, acc[q].y + a0.y);
            acc[q].z = fmaf(w, b1.x - b0.x, acc[q].z + b0.x);
            acc[q].w = fmaf(w, b1.y - b0.y, acc[q].w + b0.y);
        }
    }

    float4* pp = reinterpret_cast<float4*>(g_part) +
                 ((size_t)sp * NB + b) * MPX + tile0;
#pragma unroll
    for (int q = 0; q < PXT; q++)
        pp[tid + q * THREADS] = acc[q];
}

// ---------------------------------------------------------------------------
// Kernel 3: reduce SPLIT partials into the output.
// ---------------------------------------------------------------------------
__global__ void reduce_kernel(float4* __restrict__ out4) {
    int i = blockIdx.x * blockDim.x + threadIdx.x;   // over NB*MPX float4s
    const size_t stride = (size_t)NB * MPX;
    const float4* pp = reinterpret_cast<const float4*>(g_part);
    float4 a = pp[i];
    float4 b = pp[i + stride];
    float4 c = pp[i + 2 * stride];
    float4 d = pp[i + 3 * stride];
    float4 r;
    r.x = (a.x + b.x) + (c.x + d.x);
    r.y = (a.y + b.y) + (c.y + d.y);
    r.z = (a.z + b.z) + (c.z + d.z);
    r.w = (a.w + b.w) + (c.w + d.w);
    out4[i] = r;
}

extern "C" void kernel_launch(void* const* d_in, const int* in_sizes, int n_in,
                              void* d_out, int out_size)
{
    const float* rf = (const float*)d_in[0];   // [B, Nc, Ns, K]
    const float* g  = (const float*)d_in[1];   // [B, Nz, Nx, 3]
    const float* pr = (const float*)d_in[2];   // [B, Nc, 3]
    const float* p  = (const float*)d_in[3];   // [B, 4]
    float* out = (float*)d_out;                // [B, Nz, Nx, K]

    cudaFuncSetAttribute(das_beamform_kernel,
                         cudaFuncAttributeMaxDynamicSharedMemorySize, SMEM_BYTES);

    // 1) convert rf to fp16 scratch
    int rows = NB * NC * NS;   // 524288
    convert_rf_kernel<<<rows / THREADS, THREADS>>>((const float4*)rf);

    // 2) beamform per (tile, batch, channel-slice)
    dim3 grid(TILES, NB, SPLIT);
    das_beamform_kernel<<<grid, THREADS, SMEM_BYTES>>>(g, pr, p);

    // 3) reduce partials
    int n4 = NB * MPX;         // 131072 float4s
    reduce_kernel<<<n4 / THREADS, THREADS>>>((float4*)out);
}